// round 3
// baseline (speedup 1.0000x reference)
#include <cuda_runtime.h>
#include <math.h>

#define SEQ   2048
#define LCH   16
#define CE    128
#define CH    256
#define WE    512
#define WH    1024
#define NTAG  128
#define WBLOCKS 128

typedef unsigned long long u64;

// ---------------- device scratch ----------------
__device__ float g_WcatT[384 * 1024];     // char [c_Wih | c_Whh]^T : [k][gate_row]
__device__ float g_cbias[1024];           // c_bih + c_bhh
__device__ float g_wbias[4096];           // w_bih + w_bhh
__device__ float g_oWT[512 * 256];        // out_W k-pair-interleaved: [k2][tag][2]
__device__ float g_last[SEQ * CH];        // last char hidden per word
__device__ float g_xw[SEQ * 768];         // concat(word_emb, last_char)
__device__ float g_prew[SEQ * 4096];      // xw @ w_Wih^T + biases
__device__ float g_hs[SEQ * WH];          // word-LSTM hidden history
__device__ unsigned int g_flag[1024 * 8]; // per-warp arrival flags, 32B stride

// ---------------- f32x2 + sync helpers ----------------
__device__ __forceinline__ u64 pk2(float lo, float hi) {
    u64 r; asm("mov.b64 %0,{%1,%2};" : "=l"(r) : "f"(lo), "f"(hi)); return r;
}
__device__ __forceinline__ void upk2(u64 v, float& lo, float& hi) {
    asm("mov.b64 {%0,%1},%2;" : "=f"(lo), "=f"(hi) : "l"(v));
}
__device__ __forceinline__ u64 fma2_(u64 a, u64 b, u64 c) {
    u64 d; asm("fma.rn.f32x2 %0,%1,%2,%3;" : "=l"(d) : "l"(a), "l"(b), "l"(c)); return d;
}
__device__ __forceinline__ u64 add2_(u64 a, u64 b) {
    u64 d; asm("add.rn.f32x2 %0,%1,%2;" : "=l"(d) : "l"(a), "l"(b)); return d;
}
__device__ __forceinline__ void st_rel(unsigned* p, unsigned v) {
    asm volatile("st.release.gpu.global.u32 [%0],%1;" :: "l"(p), "r"(v) : "memory");
}
__device__ __forceinline__ unsigned ld_acq(const unsigned* p) {
    unsigned v; asm volatile("ld.acquire.gpu.global.u32 %0,[%1];" : "=r"(v) : "l"(p) : "memory"); return v;
}

__device__ __forceinline__ float sigf(float x) {
    return __fdividef(1.0f, 1.0f + __expf(-x));
}
__device__ __forceinline__ float tanhf_(float x) {
    x = fminf(fmaxf(x, -15.0f), 15.0f);
    float t = __expf(2.0f * x);
    return __fdividef(t - 1.0f, t + 1.0f);
}

// ---------------- prep ----------------
__global__ void prep_kernel(const float* __restrict__ cWih, const float* __restrict__ cWhh,
                            const float* __restrict__ cbih, const float* __restrict__ cbhh,
                            const float* __restrict__ wbih, const float* __restrict__ wbhh,
                            const float* __restrict__ outW)
{
    int idx = blockIdx.x * blockDim.x + threadIdx.x;
    int stride = gridDim.x * blockDim.x;
    for (int i = idx; i < 384 * 1024; i += stride) {
        int k = i >> 10, r = i & 1023;
        g_WcatT[i] = (k < CE) ? cWih[r * CE + k] : cWhh[r * CH + (k - CE)];
    }
    for (int i = idx; i < 1024; i += stride) g_cbias[i] = cbih[i] + cbhh[i];
    for (int i = idx; i < 4096; i += stride) g_wbias[i] = wbih[i] + wbhh[i];
    for (int i = idx; i < 512 * 256; i += stride) {
        int k2 = i >> 8, rem = i & 255;
        int tag = rem >> 1, rr = rem & 1;
        g_oWT[i] = outW[tag * 1024 + k2 * 2 + rr];
    }
    for (int i = idx; i < 1024 * 8; i += stride) g_flag[i] = 0u;
}

// ---------------- char LSTM ----------------
// 128 blocks x 256 threads, 16 words per block. Thread tid = hidden unit j.
// f32x2 packed over word pairs: accumulators a2[4 gates][8 word-pairs].
__global__ __launch_bounds__(256, 1) void char_kernel(const int* __restrict__ char_ids,
                                                      const int* __restrict__ char_lens,
                                                      const float* __restrict__ char_emb)
{
    __shared__ __align__(16) float sx[384 * 16];   // xh transposed [k][word]
    __shared__ float sh[16 * CH];                  // h per word
    __shared__ int   scid[16 * LCH];
    __shared__ int   slen[16];

    const int tid = threadIdx.x;
    const int wbase = blockIdx.x * 16;

    scid[tid] = char_ids[wbase * LCH + tid];
    if (tid < 16) slen[tid] = char_lens[wbase + tid];
    for (int i = tid; i < 16 * CH; i += 256) sh[i] = 0.0f;
    __syncthreads();

    const int j = tid;
    float bias[4];
#pragma unroll
    for (int g = 0; g < 4; ++g) bias[g] = g_cbias[g * CH + j];

    float cst[16];
#pragma unroll
    for (int w = 0; w < 16; ++w) cst[w] = 0.0f;

    const int wloc = tid & 15;

    for (int t = 0; t < LCH; ++t) {
        const int cid = scid[wloc * LCH + t];
#pragma unroll
        for (int e = 0; e < 24; ++e) {
            int idx = tid + e * 256;
            int k = idx >> 4;
            sx[idx] = (k < CE) ? char_emb[cid * CE + k]
                               : sh[wloc * CH + (k - CE)];
        }
        __syncthreads();

        u64 a2[4][8];
#pragma unroll
        for (int g = 0; g < 4; ++g) {
            u64 bp = pk2(bias[g], bias[g]);
#pragma unroll
            for (int p = 0; p < 8; ++p) a2[g][p] = bp;
        }

#pragma unroll 2
        for (int k = 0; k < 384; ++k) {
            const float* wr = &g_WcatT[k * 1024 + j];
            u64 p0 = pk2(wr[0],   wr[0]);
            u64 p1 = pk2(wr[256], wr[256]);
            u64 p2 = pk2(wr[512], wr[512]);
            u64 p3 = pk2(wr[768], wr[768]);
            const ulonglong2* bp = (const ulonglong2*)&sx[k * 16];
            ulonglong2 b0 = bp[0], b1 = bp[1], b2 = bp[2], b3 = bp[3];
            u64 bb[8] = {b0.x, b0.y, b1.x, b1.y, b2.x, b2.y, b3.x, b3.y};
#pragma unroll
            for (int p = 0; p < 8; ++p) {
                a2[0][p] = fma2_(p0, bb[p], a2[0][p]);
                a2[1][p] = fma2_(p1, bb[p], a2[1][p]);
                a2[2][p] = fma2_(p2, bb[p], a2[2][p]);
                a2[3][p] = fma2_(p3, bb[p], a2[3][p]);
            }
        }

#pragma unroll
        for (int p = 0; p < 8; ++p) {
            float i0, i1, f0, f1, gg0, gg1, o0, o1;
            upk2(a2[0][p], i0, i1);
            upk2(a2[1][p], f0, f1);
            upk2(a2[2][p], gg0, gg1);
            upk2(a2[3][p], o0, o1);
            int w0 = 2 * p, w1 = 2 * p + 1;
            float c0 = sigf(f0) * cst[w0] + sigf(i0) * tanhf_(gg0);
            cst[w0] = c0;
            float h0 = sigf(o0) * tanhf_(c0);
            sh[w0 * CH + j] = h0;
            if (t == slen[w0] - 1) g_last[(wbase + w0) * CH + j] = h0;
            float c1 = sigf(f1) * cst[w1] + sigf(i1) * tanhf_(gg1);
            cst[w1] = c1;
            float h1 = sigf(o1) * tanhf_(c1);
            sh[w1 * CH + j] = h1;
            if (t == slen[w1] - 1) g_last[(wbase + w1) * CH + j] = h1;
        }
        __syncthreads();
    }
}

// ---------------- xw concat ----------------
__global__ void xw_kernel(const int* __restrict__ word_ids, const float* __restrict__ word_emb)
{
    int t = blockIdx.x;
    int wid = word_ids[t];
    for (int i = threadIdx.x; i < 768; i += blockDim.x)
        g_xw[t * 768 + i] = (i < WE) ? word_emb[(size_t)wid * WE + i]
                                     : g_last[t * CH + (i - WE)];
}

// ---------------- pregemm: g_prew = g_xw @ w_Wih^T + wbias (f32x2) ----------------
__global__ __launch_bounds__(256, 2) void pregemm_kernel(const float* __restrict__ B)
{
    __shared__ __align__(16) float As[16][128];
    __shared__ __align__(16) float Bs[16][128];
    const int tid = threadIdx.x;
    const int tm = tid >> 4, tn = tid & 15;
    const int M0 = blockIdx.x * 128, N0 = blockIdx.y * 128;

    u64 acc2[8][4];
#pragma unroll
    for (int i = 0; i < 8; ++i)
#pragma unroll
        for (int jj = 0; jj < 4; ++jj) acc2[i][jj] = 0ull;

    for (int k0 = 0; k0 < 768; k0 += 16) {
#pragma unroll
        for (int p = 0; p < 2; ++p) {
            int f = tid + p * 256;
            int row = f >> 2, q = f & 3;
            float4 av = *(const float4*)&g_xw[(size_t)(M0 + row) * 768 + k0 + q * 4];
            As[q*4+0][row] = av.x; As[q*4+1][row] = av.y;
            As[q*4+2][row] = av.z; As[q*4+3][row] = av.w;
            float4 bv = *(const float4*)&B[(size_t)(N0 + row) * 768 + k0 + q * 4];
            Bs[q*4+0][row] = bv.x; Bs[q*4+1][row] = bv.y;
            Bs[q*4+2][row] = bv.z; Bs[q*4+3][row] = bv.w;
        }
        __syncthreads();
#pragma unroll
        for (int k = 0; k < 16; ++k) {
            float ar[8];
            *(float4*)&ar[0] = *(const float4*)&As[k][tm * 8];
            *(float4*)&ar[4] = *(const float4*)&As[k][tm * 8 + 4];
            ulonglong2 bq0 = *(const ulonglong2*)&Bs[k][tn * 8];
            ulonglong2 bq1 = *(const ulonglong2*)&Bs[k][tn * 8 + 4];
            u64 br2[4] = {bq0.x, bq0.y, bq1.x, bq1.y};
#pragma unroll
            for (int i = 0; i < 8; ++i) {
                u64 ap = pk2(ar[i], ar[i]);
#pragma unroll
                for (int jj = 0; jj < 4; ++jj)
                    acc2[i][jj] = fma2_(ap, br2[jj], acc2[i][jj]);
            }
        }
        __syncthreads();
    }

#pragma unroll
    for (int i = 0; i < 8; ++i) {
        int m = M0 + tm * 8 + i;
#pragma unroll
        for (int jj = 0; jj < 4; ++jj) {
            float lo, hi;
            upk2(acc2[i][jj], lo, hi);
            int n = N0 + tn * 8 + jj * 2;
            g_prew[(size_t)m * 4096 + n]     = lo + g_wbias[n];
            g_prew[(size_t)m * 4096 + n + 1] = hi + g_wbias[n + 1];
        }
    }
}

// ---------------- word LSTM recurrence (persistent, distributed flag barrier) ----
// 128 blocks x 256 threads. Warp = 1 hidden unit; lanes: 4 gates x 8.
// Whh register-resident as 64 packed f32x2 per thread.
__global__ __launch_bounds__(256, 1) void word_kernel(const float* __restrict__ whh)
{
    __shared__ __align__(16) float sh[WH];
    const int tid = threadIdx.x;
    const int warp = tid >> 5, lane = tid & 31;
    const int gt = lane >> 3, li = lane & 7;
    const int j = blockIdx.x * 8 + warp;
    const size_t row = (size_t)(gt * WH + j);

    u64 wv2[64];
#pragma unroll
    for (int i = 0; i < 32; ++i) {
        ulonglong2 q = *(const ulonglong2*)&whh[row * WH + li * 4 + 32 * i];
        wv2[2 * i] = q.x; wv2[2 * i + 1] = q.y;
    }

    float c = 0.0f;
    const int myflag = (blockIdx.x * 8 + warp) * 8;

    for (int t = 0; t < SEQ; ++t) {
        // prefetch pre-activations (independent of h)
        const float* pw = &g_prew[(size_t)t * 4096 + j];
        float pz0 = __ldg(&pw[0]);
        float pz1 = __ldg(&pw[1024]);
        float pz2 = __ldg(&pw[2048]);
        float pz3 = __ldg(&pw[3072]);

        // stage h_{t-1}
        float4 hv4;
        if (t == 0) hv4 = make_float4(0.f, 0.f, 0.f, 0.f);
        else        hv4 = __ldcg((const float4*)&g_hs[(size_t)(t - 1) * WH + tid * 4]);
        *(float4*)&sh[tid * 4] = hv4;
        __syncthreads();

        u64 a0 = 0ull, a1 = 0ull, a2 = 0ull, a3 = 0ull;
#pragma unroll
        for (int i = 0; i < 32; i += 2) {
            ulonglong2 h0 = *(const ulonglong2*)&sh[li * 4 + 32 * i];
            ulonglong2 h1 = *(const ulonglong2*)&sh[li * 4 + 32 * (i + 1)];
            a0 = fma2_(wv2[2*i],     h0.x, a0);
            a1 = fma2_(wv2[2*i + 1], h0.y, a1);
            a2 = fma2_(wv2[2*i + 2], h1.x, a2);
            a3 = fma2_(wv2[2*i + 3], h1.y, a3);
        }
        u64 s2 = add2_(add2_(a0, a1), add2_(a2, a3));
        float slo, shi;
        upk2(s2, slo, shi);
        float acc = slo + shi;
        acc += __shfl_down_sync(0xffffffffu, acc, 4, 8);
        acc += __shfl_down_sync(0xffffffffu, acc, 2, 8);
        acc += __shfl_down_sync(0xffffffffu, acc, 1, 8);

        float iv = __shfl_sync(0xffffffffu, acc, 0)  + pz0;
        float fv = __shfl_sync(0xffffffffu, acc, 8)  + pz1;
        float gv = __shfl_sync(0xffffffffu, acc, 16) + pz2;
        float ov = __shfl_sync(0xffffffffu, acc, 24) + pz3;

        float ig = sigf(iv), fg = sigf(fv), og = sigf(ov), gg = tanhf_(gv);
        c = fg * c + ig * gg;
        float h = og * tanhf_(c);

        if (lane == 0) {
            __stcg(&g_hs[(size_t)t * WH + j], h);
            st_rel(&g_flag[myflag], (unsigned)(t + 1));   // release: orders h store
        }

        // distributed barrier: every thread acquire-polls 4 distinct warp flags
        const unsigned tt = (unsigned)t;
        for (;;) {
            unsigned f0 = ld_acq(&g_flag[tid * 8]);
            unsigned f1 = ld_acq(&g_flag[(tid + 256) * 8]);
            unsigned f2 = ld_acq(&g_flag[(tid + 512) * 8]);
            unsigned f3 = ld_acq(&g_flag[(tid + 768) * 8]);
            if (f0 > tt && f1 > tt && f2 > tt && f3 > tt) break;
        }
        __syncthreads();
    }
}

// ---------------- output GEMM + log_softmax (f32x2, k-paired weights) ----------
__global__ __launch_bounds__(128, 2) void out_kernel(const float* __restrict__ out_b,
                                                     float* __restrict__ out)
{
    __shared__ __align__(16) float shh[8 * WH];
    __shared__ float sred[4];
    const int tid = threadIdx.x;
    const int rowbase = blockIdx.x * 8;
    const int wid = tid >> 5, lane = tid & 31;

#pragma unroll
    for (int q = 0; q < 16; ++q) {
        int off = (tid + q * 128) * 4;
        *(float4*)&shh[off] = *(const float4*)&g_hs[(size_t)rowbase * WH + off];
    }
    __syncthreads();

    u64 acc2[8];
#pragma unroll
    for (int r = 0; r < 8; ++r) acc2[r] = 0ull;

#pragma unroll 4
    for (int k2 = 0; k2 < 512; ++k2) {
        u64 wp = *(const u64*)&g_oWT[k2 * 256 + tid * 2];
#pragma unroll
        for (int r = 0; r < 8; ++r) {
            u64 hh = *(const u64*)&shh[r * WH + k2 * 2];
            acc2[r] = fma2_(wp, hh, acc2[r]);
        }
    }

    const float b = out_b[tid];
    for (int r = 0; r < 8; ++r) {
        float lo, hi;
        upk2(acc2[r], lo, hi);
        float v = lo + hi + b;
        float m = v;
#pragma unroll
        for (int o = 16; o >= 1; o >>= 1) m = fmaxf(m, __shfl_xor_sync(0xffffffffu, m, o));
        if (lane == 0) sred[wid] = m;
        __syncthreads();
        m = fmaxf(fmaxf(sred[0], sred[1]), fmaxf(sred[2], sred[3]));
        __syncthreads();
        float e = __expf(v - m);
        float s = e;
#pragma unroll
        for (int o = 16; o >= 1; o >>= 1) s += __shfl_xor_sync(0xffffffffu, s, o);
        if (lane == 0) sred[wid] = s;
        __syncthreads();
        s = sred[0] + sred[1] + sred[2] + sred[3];
        __syncthreads();
        out[(size_t)(rowbase + r) * NTAG + tid] = v - m - __logf(s);
    }
}

// ---------------- launch ----------------
extern "C" void kernel_launch(void* const* d_in, const int* in_sizes, int n_in,
                              void* d_out, int out_size)
{
    const int*   word_ids  = (const int*)d_in[0];
    const int*   char_ids  = (const int*)d_in[1];
    const int*   char_lens = (const int*)d_in[2];
    const float* char_emb  = (const float*)d_in[3];
    const float* word_emb  = (const float*)d_in[4];
    const float* c_Wih     = (const float*)d_in[5];
    const float* c_Whh     = (const float*)d_in[6];
    const float* c_bih     = (const float*)d_in[7];
    const float* c_bhh     = (const float*)d_in[8];
    const float* w_Wih     = (const float*)d_in[9];
    const float* w_Whh     = (const float*)d_in[10];
    const float* w_bih     = (const float*)d_in[11];
    const float* w_bhh     = (const float*)d_in[12];
    const float* out_W     = (const float*)d_in[13];
    const float* out_b     = (const float*)d_in[14];
    float* out = (float*)d_out;

    prep_kernel<<<512, 256>>>(c_Wih, c_Whh, c_bih, c_bhh, w_bih, w_bhh, out_W);
    char_kernel<<<128, 256>>>(char_ids, char_lens, char_emb);
    xw_kernel<<<SEQ, 256>>>(word_ids, word_emb);
    pregemm_kernel<<<dim3(16, 32), 256>>>(w_Wih);
    word_kernel<<<WBLOCKS, 256>>>(w_Whh);
    out_kernel<<<256, 128>>>(out_b, out);
}

// round 5
// speedup vs baseline: 1.0525x; 1.0525x over previous
#include <cuda_runtime.h>
#include <math.h>

#define SEQ   2048
#define LCH   16
#define CE    128
#define CH    256
#define WE    512
#define WH    1024
#define NTAG  128
#define WBLOCKS 128

typedef unsigned long long u64;

// ---------------- device scratch ----------------
__device__ float g_WcatT[384 * 1024];     // char [c_Wih | c_Whh]^T : [k][gate_row]
__device__ float g_cbias[1024];           // c_bih + c_bhh
__device__ float g_wbias[4096];           // w_bih + w_bhh
__device__ float g_oWT[512 * 256];        // out_W k-pair-interleaved: [k2][tag][2]
__device__ float g_last[SEQ * CH];        // last char hidden per word
__device__ float g_xw[SEQ * 768];         // concat(word_emb, last_char)
__device__ float g_prew[SEQ * 4096];      // xw @ w_Wih^T + biases
__device__ float g_hs[SEQ * WH];          // word-LSTM hidden history
__device__ unsigned int g_arrive[WBLOCKS * 32];  // per-block flags, 128B stride
__device__ unsigned int g_gen;                    // generation counter

// ---------------- f32x2 + sync helpers ----------------
__device__ __forceinline__ u64 pk2(float lo, float hi) {
    u64 r; asm("mov.b64 %0,{%1,%2};" : "=l"(r) : "f"(lo), "f"(hi)); return r;
}
__device__ __forceinline__ void upk2(u64 v, float& lo, float& hi) {
    asm("mov.b64 {%0,%1},%2;" : "=f"(lo), "=f"(hi) : "l"(v));
}
__device__ __forceinline__ u64 fma2_(u64 a, u64 b, u64 c) {
    u64 d; asm("fma.rn.f32x2 %0,%1,%2,%3;" : "=l"(d) : "l"(a), "l"(b), "l"(c)); return d;
}
__device__ __forceinline__ u64 add2_(u64 a, u64 b) {
    u64 d; asm("add.rn.f32x2 %0,%1,%2;" : "=l"(d) : "l"(a), "l"(b)); return d;
}
__device__ __forceinline__ void st_rel(unsigned* p, unsigned v) {
    asm volatile("st.release.gpu.global.u32 [%0],%1;" :: "l"(p), "r"(v) : "memory");
}
__device__ __forceinline__ unsigned ld_acq(const unsigned* p) {
    unsigned v; asm volatile("ld.acquire.gpu.global.u32 %0,[%1];" : "=r"(v) : "l"(p) : "memory"); return v;
}

__device__ __forceinline__ float sigf(float x) {
    return __fdividef(1.0f, 1.0f + __expf(-x));
}
__device__ __forceinline__ float tanhf_(float x) {
    x = fminf(fmaxf(x, -15.0f), 15.0f);
    float t = __expf(2.0f * x);
    return __fdividef(t - 1.0f, t + 1.0f);
}

// ---------------- prep ----------------
__global__ void prep_kernel(const float* __restrict__ cWih, const float* __restrict__ cWhh,
                            const float* __restrict__ cbih, const float* __restrict__ cbhh,
                            const float* __restrict__ wbih, const float* __restrict__ wbhh,
                            const float* __restrict__ outW)
{
    int idx = blockIdx.x * blockDim.x + threadIdx.x;
    int stride = gridDim.x * blockDim.x;
    for (int i = idx; i < 384 * 1024; i += stride) {
        int k = i >> 10, r = i & 1023;
        g_WcatT[i] = (k < CE) ? cWih[r * CE + k] : cWhh[r * CH + (k - CE)];
    }
    for (int i = idx; i < 1024; i += stride) g_cbias[i] = cbih[i] + cbhh[i];
    for (int i = idx; i < 4096; i += stride) g_wbias[i] = wbih[i] + wbhh[i];
    for (int i = idx; i < 512 * 256; i += stride) {
        int k2 = i >> 8, rem = i & 255;
        int tag = rem >> 1, rr = rem & 1;
        g_oWT[i] = outW[tag * 1024 + k2 * 2 + rr];
    }
    for (int i = idx; i < WBLOCKS * 32; i += stride) g_arrive[i] = 0u;
    if (idx == 0) g_gen = 0u;
}

// ---------------- char LSTM ----------------
// 128 blocks x 256 threads, 16 words per block. Thread tid = hidden unit j.
__global__ __launch_bounds__(256, 1) void char_kernel(const int* __restrict__ char_ids,
                                                      const int* __restrict__ char_lens,
                                                      const float* __restrict__ char_emb)
{
    __shared__ __align__(16) float sx[384 * 16];   // xh transposed [k][word]
    __shared__ float sh[16 * CH];                  // h per word
    __shared__ int   scid[16 * LCH];
    __shared__ int   slen[16];

    const int tid = threadIdx.x;
    const int wbase = blockIdx.x * 16;

    scid[tid] = char_ids[wbase * LCH + tid];
    if (tid < 16) slen[tid] = char_lens[wbase + tid];
    for (int i = tid; i < 16 * CH; i += 256) sh[i] = 0.0f;
    __syncthreads();

    const int j = tid;
    float bias[4];
#pragma unroll
    for (int g = 0; g < 4; ++g) bias[g] = g_cbias[g * CH + j];

    float cst[16];
#pragma unroll
    for (int w = 0; w < 16; ++w) cst[w] = 0.0f;

    const int wloc = tid & 15;

    for (int t = 0; t < LCH; ++t) {
        const int cid = scid[wloc * LCH + t];
#pragma unroll
        for (int e = 0; e < 24; ++e) {
            int idx = tid + e * 256;
            int k = idx >> 4;
            sx[idx] = (k < CE) ? char_emb[cid * CE + k]
                               : sh[wloc * CH + (k - CE)];
        }
        __syncthreads();

        u64 a2[4][8];
#pragma unroll
        for (int g = 0; g < 4; ++g) {
            u64 bp = pk2(bias[g], bias[g]);
#pragma unroll
            for (int p = 0; p < 8; ++p) a2[g][p] = bp;
        }

#pragma unroll 2
        for (int k = 0; k < 384; ++k) {
            const float* wr = &g_WcatT[k * 1024 + j];
            u64 p0 = pk2(wr[0],   wr[0]);
            u64 p1 = pk2(wr[256], wr[256]);
            u64 p2 = pk2(wr[512], wr[512]);
            u64 p3 = pk2(wr[768], wr[768]);
            const ulonglong2* bp = (const ulonglong2*)&sx[k * 16];
            ulonglong2 b0 = bp[0], b1 = bp[1], b2 = bp[2], b3 = bp[3];
            u64 bb[8] = {b0.x, b0.y, b1.x, b1.y, b2.x, b2.y, b3.x, b3.y};
#pragma unroll
            for (int p = 0; p < 8; ++p) {
                a2[0][p] = fma2_(p0, bb[p], a2[0][p]);
                a2[1][p] = fma2_(p1, bb[p], a2[1][p]);
                a2[2][p] = fma2_(p2, bb[p], a2[2][p]);
                a2[3][p] = fma2_(p3, bb[p], a2[3][p]);
            }
        }

#pragma unroll
        for (int p = 0; p < 8; ++p) {
            float i0, i1, f0, f1, gg0, gg1, o0, o1;
            upk2(a2[0][p], i0, i1);
            upk2(a2[1][p], f0, f1);
            upk2(a2[2][p], gg0, gg1);
            upk2(a2[3][p], o0, o1);
            int w0 = 2 * p, w1 = 2 * p + 1;
            float c0 = sigf(f0) * cst[w0] + sigf(i0) * tanhf_(gg0);
            cst[w0] = c0;
            float h0 = sigf(o0) * tanhf_(c0);
            sh[w0 * CH + j] = h0;
            if (t == slen[w0] - 1) g_last[(wbase + w0) * CH + j] = h0;
            float c1 = sigf(f1) * cst[w1] + sigf(i1) * tanhf_(gg1);
            cst[w1] = c1;
            float h1 = sigf(o1) * tanhf_(c1);
            sh[w1 * CH + j] = h1;
            if (t == slen[w1] - 1) g_last[(wbase + w1) * CH + j] = h1;
        }
        __syncthreads();
    }
}

// ---------------- xw concat ----------------
__global__ void xw_kernel(const int* __restrict__ word_ids, const float* __restrict__ word_emb)
{
    int t = blockIdx.x;
    int wid = word_ids[t];
    for (int i = threadIdx.x; i < 768; i += blockDim.x)
        g_xw[t * 768 + i] = (i < WE) ? word_emb[(size_t)wid * WE + i]
                                     : g_last[t * CH + (i - WE)];
}

// ---------------- pregemm: g_prew = g_xw @ w_Wih^T + wbias ----------------
__global__ __launch_bounds__(256, 2) void pregemm_kernel(const float* __restrict__ B)
{
    __shared__ float As[16][128];
    __shared__ float Bs[16][128];
    const int tid = threadIdx.x;
    const int tm = tid >> 4, tn = tid & 15;
    const int M0 = blockIdx.x * 128, N0 = blockIdx.y * 128;

    float acc[8][8];
#pragma unroll
    for (int i = 0; i < 8; ++i)
#pragma unroll
        for (int jj = 0; jj < 8; ++jj) acc[i][jj] = 0.0f;

    for (int k0 = 0; k0 < 768; k0 += 16) {
#pragma unroll
        for (int p = 0; p < 2; ++p) {
            int f = tid + p * 256;
            int row = f >> 2, q = f & 3;
            float4 av = *(const float4*)&g_xw[(size_t)(M0 + row) * 768 + k0 + q * 4];
            As[q*4+0][row] = av.x; As[q*4+1][row] = av.y;
            As[q*4+2][row] = av.z; As[q*4+3][row] = av.w;
            float4 bv = *(const float4*)&B[(size_t)(N0 + row) * 768 + k0 + q * 4];
            Bs[q*4+0][row] = bv.x; Bs[q*4+1][row] = bv.y;
            Bs[q*4+2][row] = bv.z; Bs[q*4+3][row] = bv.w;
        }
        __syncthreads();
#pragma unroll
        for (int k = 0; k < 16; ++k) {
            float ar[8], br[8];
            *(float4*)&ar[0] = *(const float4*)&As[k][tm * 8];
            *(float4*)&ar[4] = *(const float4*)&As[k][tm * 8 + 4];
            *(float4*)&br[0] = *(const float4*)&Bs[k][tn * 8];
            *(float4*)&br[4] = *(const float4*)&Bs[k][tn * 8 + 4];
#pragma unroll
            for (int i = 0; i < 8; ++i)
#pragma unroll
                for (int jj = 0; jj < 8; ++jj)
                    acc[i][jj] = fmaf(ar[i], br[jj], acc[i][jj]);
        }
        __syncthreads();
    }

#pragma unroll
    for (int i = 0; i < 8; ++i) {
        int m = M0 + tm * 8 + i;
#pragma unroll
        for (int jj = 0; jj < 8; ++jj) {
            int n = N0 + tn * 8 + jj;
            g_prew[(size_t)m * 4096 + n] = acc[i][jj] + g_wbias[n];
        }
    }
}

// ---------------- word LSTM recurrence (persistent, hierarchical barrier) --------
// 128 blocks x 256 threads. Warp = 1 hidden unit; lanes: 4 gates x 8.
__global__ __launch_bounds__(256, 1) void word_kernel(const float* __restrict__ whh)
{
    __shared__ __align__(16) float sh[WH];
    const int tid = threadIdx.x;
    const int warp = tid >> 5, lane = tid & 31;
    const int gt = lane >> 3, li = lane & 7;
    const int j = blockIdx.x * 8 + warp;
    const size_t row = (size_t)(gt * WH + j);

    u64 wv2[64];
#pragma unroll
    for (int i = 0; i < 32; ++i) {
        ulonglong2 q = *(const ulonglong2*)&whh[row * WH + li * 4 + 32 * i];
        wv2[2 * i] = q.x; wv2[2 * i + 1] = q.y;
    }

    float c = 0.0f;

    for (int t = 0; t < SEQ; ++t) {
        // prefetch pre-activations (independent of h)
        const float* pw = &g_prew[(size_t)t * 4096 + j];
        float pz0 = __ldg(&pw[0]);
        float pz1 = __ldg(&pw[1024]);
        float pz2 = __ldg(&pw[2048]);
        float pz3 = __ldg(&pw[3072]);

        // stage h_{t-1}
        float4 hv4;
        if (t == 0) hv4 = make_float4(0.f, 0.f, 0.f, 0.f);
        else        hv4 = __ldcg((const float4*)&g_hs[(size_t)(t - 1) * WH + tid * 4]);
        *(float4*)&sh[tid * 4] = hv4;
        __syncthreads();

        u64 a0 = 0ull, a1 = 0ull, a2 = 0ull, a3 = 0ull;
#pragma unroll
        for (int i = 0; i < 32; i += 2) {
            ulonglong2 h0 = *(const ulonglong2*)&sh[li * 4 + 32 * i];
            ulonglong2 h1 = *(const ulonglong2*)&sh[li * 4 + 32 * (i + 1)];
            a0 = fma2_(wv2[2*i],     h0.x, a0);
            a1 = fma2_(wv2[2*i + 1], h0.y, a1);
            a2 = fma2_(wv2[2*i + 2], h1.x, a2);
            a3 = fma2_(wv2[2*i + 3], h1.y, a3);
        }
        u64 s2 = add2_(add2_(a0, a1), add2_(a2, a3));
        float slo, shi;
        upk2(s2, slo, shi);
        float acc = slo + shi;
        acc += __shfl_down_sync(0xffffffffu, acc, 4, 8);
        acc += __shfl_down_sync(0xffffffffu, acc, 2, 8);
        acc += __shfl_down_sync(0xffffffffu, acc, 1, 8);

        float iv = __shfl_sync(0xffffffffu, acc, 0)  + pz0;
        float fv = __shfl_sync(0xffffffffu, acc, 8)  + pz1;
        float gv = __shfl_sync(0xffffffffu, acc, 16) + pz2;
        float ov = __shfl_sync(0xffffffffu, acc, 24) + pz3;

        float ig = sigf(iv), fg = sigf(fv), og = sigf(ov), gg = tanhf_(gv);
        c = fg * c + ig * gg;
        float h = og * tanhf_(c);

        if (lane == 0) __stcg(&g_hs[(size_t)t * WH + j], h);
        __syncthreads();                        // all 8 warps' h stores issued

        // --- hierarchical barrier ---
        const unsigned tt = (unsigned)t;
        if (tid == 0) st_rel(&g_arrive[blockIdx.x * 32], tt + 1u);
        if (blockIdx.x == 0) {
            if (tid < WBLOCKS) {
                while (ld_acq(&g_arrive[tid * 32]) <= tt) { }   // tight: latency-critical
            }
            __syncthreads();
            if (tid == 0) st_rel(&g_gen, tt + 1u);
        } else if (tid == 0) {
            while (ld_acq(&g_gen) <= tt) { __nanosleep(32); }   // light poll on shared line
        }
        __syncthreads();
    }
}

// ---------------- output GEMM + log_softmax (f32x2, k-paired weights) ----------
__global__ __launch_bounds__(128, 2) void out_kernel(const float* __restrict__ out_b,
                                                     float* __restrict__ out)
{
    __shared__ __align__(16) float shh[8 * WH];
    __shared__ float sred[4];
    const int tid = threadIdx.x;
    const int rowbase = blockIdx.x * 8;
    const int wid = tid >> 5, lane = tid & 31;

#pragma unroll
    for (int q = 0; q < 16; ++q) {
        int off = (tid + q * 128) * 4;
        *(float4*)&shh[off] = *(const float4*)&g_hs[(size_t)rowbase * WH + off];
    }
    __syncthreads();

    u64 acc2[8];
#pragma unroll
    for (int r = 0; r < 8; ++r) acc2[r] = 0ull;

#pragma unroll 4
    for (int k2 = 0; k2 < 512; ++k2) {
        u64 wp = *(const u64*)&g_oWT[k2 * 256 + tid * 2];
#pragma unroll
        for (int r = 0; r < 8; ++r) {
            u64 hh = *(const u64*)&shh[r * WH + k2 * 2];
            acc2[r] = fma2_(wp, hh, acc2[r]);
        }
    }

    const float b = out_b[tid];
    for (int r = 0; r < 8; ++r) {
        float lo, hi;
        upk2(acc2[r], lo, hi);
        float v = lo + hi + b;
        float m = v;
#pragma unroll
        for (int o = 16; o >= 1; o >>= 1) m = fmaxf(m, __shfl_xor_sync(0xffffffffu, m, o));
        if (lane == 0) sred[wid] = m;
        __syncthreads();
        m = fmaxf(fmaxf(sred[0], sred[1]), fmaxf(sred[2], sred[3]));
        __syncthreads();
        float e = __expf(v - m);
        float s = e;
#pragma unroll
        for (int o = 16; o >= 1; o >>= 1) s += __shfl_xor_sync(0xffffffffu, s, o);
        if (lane == 0) sred[wid] = s;
        __syncthreads();
        s = sred[0] + sred[1] + sred[2] + sred[3];
        __syncthreads();
        out[(size_t)(rowbase + r) * NTAG + tid] = v - m - __logf(s);
    }
}

// ---------------- launch ----------------
extern "C" void kernel_launch(void* const* d_in, const int* in_sizes, int n_in,
                              void* d_out, int out_size)
{
    const int*   word_ids  = (const int*)d_in[0];
    const int*   char_ids  = (const int*)d_in[1];
    const int*   char_lens = (const int*)d_in[2];
    const float* char_emb  = (const float*)d_in[3];
    const float* word_emb  = (const float*)d_in[4];
    const float* c_Wih     = (const float*)d_in[5];
    const float* c_Whh     = (const float*)d_in[6];
    const float* c_bih     = (const float*)d_in[7];
    const float* c_bhh     = (const float*)d_in[8];
    const float* w_Wih     = (const float*)d_in[9];
    const float* w_Whh     = (const float*)d_in[10];
    const float* w_bih     = (const float*)d_in[11];
    const float* w_bhh     = (const float*)d_in[12];
    const float* out_W     = (const float*)d_in[13];
    const float* out_b     = (const float*)d_in[14];
    float* out = (float*)d_out;

    prep_kernel<<<512, 256>>>(c_Wih, c_Whh, c_bih, c_bhh, w_bih, w_bhh, out_W);
    char_kernel<<<128, 256>>>(char_ids, char_lens, char_emb);
    xw_kernel<<<SEQ, 256>>>(word_ids, word_emb);
    pregemm_kernel<<<dim3(16, 32), 256>>>(w_Wih);
    word_kernel<<<WBLOCKS, 256>>>(w_Whh);
    out_kernel<<<256, 128>>>(out_b, out);
}